// round 12
// baseline (speedup 1.0000x reference)
#include <cuda_runtime.h>

// ---------------------------------------------------------------------------
// NLIF recurrent spiking net — persistent kernel.
// Round 12: pipelined quarter-sync. 4 quarter release-counters, a dedicated
// sync warp (warp 0 of 9) doing concurrent per-quarter discovery + the state
// update tail, and 8 compute warps gating each FMA chunk on its quarter's
// SMEM flag (straggler quarters hide under earlier chunks' FMA).
// ---------------------------------------------------------------------------

#define NN 2048
#define TT 2048
#define G  147           // CTAs, 1 per SM
#define CPT 14           // columns per CTA
#define NTHREADS 288     // warp 0 = sync/update; warps 1..8 = compute (256 thr)
#define CWARPS 8
#define CSTRF 4096       // floats per column slab: 2048 rows x (ws,wf)

#define SMEM_BYTES ((CPT * CSTRF + 16 * CWARPS) * 4)

// quarter of CTA b: [0,36]=0, [37,73]=1, [74,110]=2, [111,146]=3
// chunk k of the state gather needs quarters 0..k complete.

// persistent device state (no allocations allowed)
__device__ __align__(16) float2 g_state[2][NN];   // (s, s_fast), double-buffered
__device__ unsigned g_q[4][TT + 2];               // per-quarter step counters + epoch slot
__device__ float g_part[TT * G * 2];              // per-CTA readout partials

__device__ __forceinline__ unsigned ld_relaxed_u32(const unsigned* p) {
    unsigned v;
    asm volatile("ld.relaxed.gpu.global.u32 %0, [%1];" : "=r"(v) : "l"(p) : "memory");
    return v;
}
__device__ __forceinline__ void red_release_add(unsigned* p, unsigned v) {
    asm volatile("red.release.gpu.global.add.u32 [%0], %1;" :: "l"(p), "r"(v) : "memory");
}

__global__ void __launch_bounds__(NTHREADS, 1)
nlif_kernel(const float* __restrict__ x_in,    // [T][2]
            const float* __restrict__ W_syn,   // [N][N]
            const float* __restrict__ W_fast,  // [N][N]
            const float* __restrict__ W_in,    // [2][N]
            const float* __restrict__ I_o,     // [N]
            const float* __restrict__ O,       // [2][N]
            float* __restrict__ out_spikes,    // [T][N]
            float* __restrict__ out_vs)        // [T][N]
{
    extern __shared__ float smem[];
    float* Wc  = smem;                    // [CPT][CSTRF]
    float* red = smem + CPT * CSTRF;      // [16][CWARPS]
    __shared__ unsigned sflag[4];
    volatile unsigned* vf = sflag;

    const int tid  = threadIdx.x;
    const int warp = tid >> 5;
    const int lane = tid & 31;
    const int b    = blockIdx.x;
    const int j0   = b * CPT;
    const int myq  = (b >= 111) ? 3 : (b >= 74) ? 2 : (b >= 37) ? 1 : 0;

    if (tid < 4) sflag[tid] = 0;

    // ---- stage weight columns into SMEM (9 warps) ----
    for (int i = warp; i < NN; i += 9) {
        if (lane < CPT) {
            const int jj = j0 + lane;
            float ws = 0.f, wf = 0.f;
            if (jj < NN) {
                ws = W_syn[(size_t)i * NN + jj];
                wf = W_fast[(size_t)i * NN + jj];
                if (i == jj) ws = 0.f;              // self-recurrence mask
            }
            const int p = i >> 1, r = i & 1;
            Wc[lane * CSTRF + p * 4 + r * 2 + 0] = ws;
            Wc[lane * CSTRF + p * 4 + r * 2 + 1] = wf;
        }
    }
    __syncthreads();

    // ---- compute warps: k=1,2,3 weight chunks to registers ----
    const int ct = tid - 32;              // 0..255 for warps 1..8
    float4 wr[CPT][3];
    if (warp > 0) {
        #pragma unroll
        for (int c = 0; c < CPT; c++) {
            #pragma unroll
            for (int kk = 0; kk < 3; kk++) {
                const int p = (kk + 1) * 256 + ct;
                wr[c][kk] = *reinterpret_cast<const float4*>(&Wc[c * CSTRF + p * 4]);
            }
        }
    }

    // ---- sync warp: per-lane quarter target (lanes 0..3 own quarters 0..3) ----
    unsigned tq = 0;
    if (warp == 0) {
        const int k = lane & 3;
        const unsigned nq = (k == 3) ? 36u : 37u;
        tq = ld_relaxed_u32(&g_q[k][TT + 1]) + nq;   // epoch base + quarter count
    }

    // ---- per-column persistent state in sync-warp registers ----
    const int j = j0 + lane;
    const bool active = (warp == 0) && (lane < CPT) && (j < NN);
    float v = 0.f, s = 0.f;
    float wi0 = 0.f, wi1 = 0.f, io = 0.f, o0 = 0.f, o1 = 0.f;
    if (active) {
        wi0 = W_in[j];
        wi1 = W_in[NN + j];
        io  = I_o[j];
        o0  = O[j];
        o1  = O[NN + j];
        __stcg(&g_state[0][j], make_float2(0.f, 0.f));   // t=0 reads parity-0 zeros
    }
    if (warp == 0 && lane == 0) red_release_add(&g_q[myq][0], 1u);  // initial publish

    float x0 = 0.f, x1 = 0.f;

    for (int t = 0; t < TT; t++) {
        const int rb = t & 1;
        const int wb = rb ^ 1;
        const unsigned tpub = (unsigned)(t + 1);
        const float2* srow = g_state[rb];

        if (warp == 0) {
            x0 = __ldg(&x_in[2 * t]);
            x1 = __ldg(&x_in[2 * t + 1]);
            // concurrent per-quarter discovery: lanes 0..3 poll their quarter,
            // posting the SMEM flag the moment it completes.
            const int k = lane & 3;
            const unsigned* qp = &g_q[k][t];
            bool ok = (lane >= 4);
            bool posted = (lane >= 4);
            unsigned bal;
            do {
                if (!ok) ok = ((int)(ld_relaxed_u32(qp) - tq) >= 0);
                if (ok && !posted) { vf[k] = tpub; posted = true; }
                bal = __ballot_sync(0xffffffffu, ok);
            } while (bal != 0xffffffffu);
        } else {
            // ---- compute warps: chunk pipeline gated on quarter flags ----
            float4 st0, st1, st2, st3;
            bool i1 = false, i2 = false, i3 = false;
            float acc[16];

            while (vf[0] < tpub) {}
            st0 = __ldcg(reinterpret_cast<const float4*>(&srow[2 * (0 * 256 + ct)]));
            if (vf[1] >= tpub) { st1 = __ldcg(reinterpret_cast<const float4*>(&srow[2 * (1 * 256 + ct)])); i1 = true; }
            if (vf[2] >= tpub) { st2 = __ldcg(reinterpret_cast<const float4*>(&srow[2 * (2 * 256 + ct)])); i2 = true; }
            if (vf[3] >= tpub) { st3 = __ldcg(reinterpret_cast<const float4*>(&srow[2 * (3 * 256 + ct)])); i3 = true; }

            // chunk 0 (weights from SMEM)
            #pragma unroll
            for (int c = 0; c < CPT; c++) {
                const float4 w = *reinterpret_cast<const float4*>(&Wc[c * CSTRF + ct * 4]);
                float a = 0.f;
                a = fmaf(st0.x, w.x, a);
                a = fmaf(st0.y, w.y, a);
                a = fmaf(st0.z, w.z, a);
                a = fmaf(st0.w, w.w, a);
                acc[c] = a;
            }

            if (!i1) { while (vf[1] < tpub) {} st1 = __ldcg(reinterpret_cast<const float4*>(&srow[2 * (1 * 256 + ct)])); }
            if (!i2 && vf[2] >= tpub) { st2 = __ldcg(reinterpret_cast<const float4*>(&srow[2 * (2 * 256 + ct)])); i2 = true; }
            if (!i3 && vf[3] >= tpub) { st3 = __ldcg(reinterpret_cast<const float4*>(&srow[2 * (3 * 256 + ct)])); i3 = true; }

            #pragma unroll
            for (int c = 0; c < CPT; c++) {
                const float4 w = wr[c][0];
                float a = acc[c];
                a = fmaf(st1.x, w.x, a);
                a = fmaf(st1.y, w.y, a);
                a = fmaf(st1.z, w.z, a);
                a = fmaf(st1.w, w.w, a);
                acc[c] = a;
            }

            if (!i2) { while (vf[2] < tpub) {} st2 = __ldcg(reinterpret_cast<const float4*>(&srow[2 * (2 * 256 + ct)])); }
            if (!i3 && vf[3] >= tpub) { st3 = __ldcg(reinterpret_cast<const float4*>(&srow[2 * (3 * 256 + ct)])); i3 = true; }

            #pragma unroll
            for (int c = 0; c < CPT; c++) {
                const float4 w = wr[c][1];
                float a = acc[c];
                a = fmaf(st2.x, w.x, a);
                a = fmaf(st2.y, w.y, a);
                a = fmaf(st2.z, w.z, a);
                a = fmaf(st2.w, w.w, a);
                acc[c] = a;
            }

            if (!i3) { while (vf[3] < tpub) {} st3 = __ldcg(reinterpret_cast<const float4*>(&srow[2 * (3 * 256 + ct)])); }

            #pragma unroll
            for (int c = 0; c < CPT; c++) {
                const float4 w = wr[c][2];
                float a = acc[c];
                a = fmaf(st3.x, w.x, a);
                a = fmaf(st3.y, w.y, a);
                a = fmaf(st3.z, w.z, a);
                a = fmaf(st3.w, w.w, a);
                acc[c] = a;
            }
            acc[14] = 0.f;
            acc[15] = 0.f;

            // butterfly multi-column reduce: 16 SHFL + 16 FADD per warp
            #pragma unroll
            for (int i = 0; i < 8; i++) {
                const float give = (lane & 16) ? acc[i] : acc[i + 8];
                const float got  = __shfl_xor_sync(0xffffffffu, give, 16);
                const float keep = (lane & 16) ? acc[i + 8] : acc[i];
                acc[i] = keep + got;
            }
            #pragma unroll
            for (int i = 0; i < 4; i++) {
                const float give = (lane & 8) ? acc[i] : acc[i + 4];
                const float got  = __shfl_xor_sync(0xffffffffu, give, 8);
                const float keep = (lane & 8) ? acc[i + 4] : acc[i];
                acc[i] = keep + got;
            }
            #pragma unroll
            for (int i = 0; i < 2; i++) {
                const float give = (lane & 4) ? acc[i] : acc[i + 2];
                const float got  = __shfl_xor_sync(0xffffffffu, give, 4);
                const float keep = (lane & 4) ? acc[i + 2] : acc[i];
                acc[i] = keep + got;
            }
            {
                const float give = (lane & 2) ? acc[0] : acc[1];
                const float got  = __shfl_xor_sync(0xffffffffu, give, 2);
                const float keep = (lane & 2) ? acc[1] : acc[0];
                acc[0] = keep + got;
            }
            acc[0] += __shfl_xor_sync(0xffffffffu, acc[0], 1);

            if ((lane & 1) == 0) red[((lane >> 1) & 15) * CWARPS + (warp - 1)] = acc[0];
        }
        __syncthreads();

        if (warp == 0) {
            float r0 = 0.f, r1 = 0.f;
            float s_new = 0.f, gd = 0.f, spk = 0.f, v_new = 0.f;
            if (active) {
                const float4 p0 = *reinterpret_cast<const float4*>(&red[lane * CWARPS]);
                const float4 p1 = *reinterpret_cast<const float4*>(&red[lane * CWARPS + 4]);
                const float sum = ((p0.x + p0.y) + (p0.z + p0.w)) +
                                  ((p1.x + p1.y) + (p1.z + p1.w));

                const float I_tot  = sum + x0 * wi0 + x1 * wi1 + io;
                const float dv     = (I_tot - v) / 10.0f;          // TAU_M
                const float v_next = v + dv;
                const float gating = fminf(fmaxf(v_next, -1.f), 1.f);
                const float dvc    = fminf(fmaxf(dv, -1.f), 1.f);
                gd                 = gating * dvc;
                s_new              = s + (gd - s) / 10.0f;         // TAU_S
                spk                = (v_next >=  1.f) ? 1.f : 0.f;
                const float sn     = (v_next <= -1.f) ? 1.f : 0.f;
                v_new              = (1.f + spk - sn) * v_next;    // matches reference exactly

                v = v_new; s = s_new;
                __stcg(&g_state[wb][j], make_float2(s_new, gd));
            }
            // publish progress FIRST (release orders the state stores above)
            if (lane == 0) red_release_add(&g_q[myq][t + 1], 1u);

            // non-critical outputs after the release
            if (active) {
                out_spikes[(size_t)t * NN + j] = spk;
                out_vs[(size_t)t * NN + j]     = v_new;
                r0 = o0 * s_new;
                r1 = o1 * s_new;
            }
            #pragma unroll
            for (int o = 16; o; o >>= 1) {
                r0 += __shfl_down_sync(0xffffffffu, r0, o);
                r1 += __shfl_down_sync(0xffffffffu, r1, o);
            }
            if (lane == 0) {
                g_part[((size_t)t * G + b) * 2 + 0] = r0;
                g_part[((size_t)t * G + b) * 2 + 1] = r1;
            }
        }
    }

    // bump this quarter's epoch slot (one per CTA per replay)
    if (warp == 0 && lane == 0) red_release_add(&g_q[myq][TT + 1], 1u);
}

// epilogue: one warp per timestep, coalesced float2 loads + shfl reduce
__global__ void readout_kernel(float* __restrict__ out_ro) {
    const int t    = blockIdx.x * (blockDim.x >> 5) + (threadIdx.x >> 5);
    const int lane = threadIdx.x & 31;
    if (t < TT) {
        const float2* p = reinterpret_cast<const float2*>(&g_part[(size_t)t * G * 2]);
        float a = 0.f, c = 0.f;
        for (int bb = lane; bb < G; bb += 32) {
            const float2 pv = p[bb];
            a += pv.x;
            c += pv.y;
        }
        #pragma unroll
        for (int o = 16; o; o >>= 1) {
            a += __shfl_down_sync(0xffffffffu, a, o);
            c += __shfl_down_sync(0xffffffffu, c, o);
        }
        if (lane == 0) {
            out_ro[2 * t]     = a;
            out_ro[2 * t + 1] = c;
        }
    }
}

extern "C" void kernel_launch(void* const* d_in, const int* in_sizes, int n_in,
                              void* d_out, int out_size) {
    const float* x_in   = (const float*)d_in[0];
    const float* W_syn  = (const float*)d_in[1];
    const float* W_fast = (const float*)d_in[2];
    const float* W_in   = (const float*)d_in[3];
    const float* I_o    = (const float*)d_in[4];
    const float* O      = (const float*)d_in[5];

    float* out        = (float*)d_out;
    float* out_spikes = out;                                // [T][N]
    float* out_ro     = out + (size_t)TT * NN;              // [T][2]
    float* out_vs     = out + (size_t)TT * NN + 2 * TT;     // [T][N]

    cudaFuncSetAttribute(nlif_kernel,
                         cudaFuncAttributeMaxDynamicSharedMemorySize, SMEM_BYTES);

    nlif_kernel<<<G, NTHREADS, SMEM_BYTES>>>(x_in, W_syn, W_fast, W_in, I_o, O,
                                             out_spikes, out_vs);
    readout_kernel<<<TT / 8, 256>>>(out_ro);
}

// round 14
// speedup vs baseline: 1.7906x; 1.7906x over previous
#include <cuda_runtime.h>

// ---------------------------------------------------------------------------
// NLIF recurrent spiking net — persistent kernel.
// Round 13 resubmit (infra flake): R11 compute core untouched. ONE change,
// confined to warp-0 sync: 4 quarter release-counters on separate L2 lines
// (spreads 147 REDs that previously collided with poll reads on one slice),
// polled concurrently by lanes 0..3 with a ballot exit.
// ---------------------------------------------------------------------------

#define NN 2048
#define TT 2048
#define G  147           // CTAs, 1 per SM (all co-resident on 148 SMs)
#define CPT 14           // columns per CTA (147*14 = 2058 >= 2048)
#define NTHREADS 256
#define NWARPS 8
#define CSTRF 4096       // floats per column slab: 2048 rows x (ws,wf)

#define SMEM_BYTES ((CPT * CSTRF + 16 * NWARPS) * 4)

// quarter of CTA b: [0,36]=0, [37,73]=1, [74,110]=2, [111,146]=3 (37/37/37/36)

// persistent device state (no allocations allowed)
__device__ __align__(16) float2 g_state[2][NN];   // (s, s_fast), double-buffered
__device__ unsigned g_q[4][TT + 2];               // per-quarter counters + epoch slot
__device__ float g_part[TT * G * 2];              // per-CTA readout partials

__device__ __forceinline__ unsigned ld_relaxed_u32(const unsigned* p) {
    unsigned v;
    asm volatile("ld.relaxed.gpu.global.u32 %0, [%1];" : "=r"(v) : "l"(p) : "memory");
    return v;
}
__device__ __forceinline__ void red_release_add(unsigned* p, unsigned v) {
    asm volatile("red.release.gpu.global.add.u32 [%0], %1;" :: "l"(p), "r"(v) : "memory");
}

__global__ void __launch_bounds__(NTHREADS, 1)
nlif_kernel(const float* __restrict__ x_in,    // [T][2]
            const float* __restrict__ W_syn,   // [N][N]
            const float* __restrict__ W_fast,  // [N][N]
            const float* __restrict__ W_in,    // [2][N]
            const float* __restrict__ I_o,     // [N]
            const float* __restrict__ O,       // [2][N]
            float* __restrict__ out_spikes,    // [T][N]
            float* __restrict__ out_vs)        // [T][N]
{
    extern __shared__ float smem[];
    float* Wc  = smem;                    // [CPT][CSTRF] : per pair p, (ws0,wf0,ws1,wf1)
    float* red = smem + CPT * CSTRF;      // [16][NWARPS]

    const int tid  = threadIdx.x;
    const int warp = tid >> 5;
    const int lane = tid & 31;
    const int b    = blockIdx.x;
    const int j0   = b * CPT;
    const int myq  = (b >= 111) ? 3 : (b >= 74) ? 2 : (b >= 37) ? 1 : 0;

    // per-quarter epoch base: each launch adds nq to quarter k's counters and
    // +nq to its epoch slot (one bump per CTA of that quarter at kernel end).
    unsigned tq = 0;
    if (warp == 0 && lane < 4) {
        const unsigned nq = (lane == 3) ? 36u : 37u;
        tq = ld_relaxed_u32(&g_q[lane][TT + 1]) + nq;
    }

    // ---- stage weight columns into SMEM, interleaved (ws,wf) per row ----
    for (int i = warp; i < NN; i += NWARPS) {
        if (lane < CPT) {
            const int jj = j0 + lane;
            float ws = 0.f, wf = 0.f;
            if (jj < NN) {
                ws = W_syn[(size_t)i * NN + jj];
                wf = W_fast[(size_t)i * NN + jj];
                if (i == jj) ws = 0.f;              // self-recurrence mask
            }
            const int p = i >> 1, r = i & 1;
            Wc[lane * CSTRF + p * 4 + r * 2 + 0] = ws;
            Wc[lane * CSTRF + p * 4 + r * 2 + 1] = wf;
        }
    }
    __syncthreads();

    // ---- pull k=1,2,3 weight chunks into registers (168 regs/thread) ----
    float4 wr[CPT][3];
    #pragma unroll
    for (int c = 0; c < CPT; c++) {
        #pragma unroll
        for (int kk = 0; kk < 3; kk++) {
            const int p = (kk + 1) * NTHREADS + tid;
            wr[c][kk] = *reinterpret_cast<const float4*>(&Wc[c * CSTRF + p * 4]);
        }
    }

    // ---- per-column persistent state in warp-0 registers ----
    const int j = j0 + lane;
    const bool active = (warp == 0) && (lane < CPT) && (j < NN);
    float v = 0.f, s = 0.f;
    float wi0 = 0.f, wi1 = 0.f, io = 0.f, o0 = 0.f, o1 = 0.f;
    if (active) {
        wi0 = W_in[j];
        wi1 = W_in[NN + j];
        io  = I_o[j];
        o0  = O[j];
        o1  = O[NN + j];
        __stcg(&g_state[0][j], make_float2(0.f, 0.f));   // t=0 reads parity-0 zeros
    }
    if (warp == 0 && lane == 0) red_release_add(&g_q[myq][0], 1u);  // initial publish

    for (int t = 0; t < TT; t++) {
        const int rb = t & 1;
        const int wb = rb ^ 1;

        float x0 = 0.f, x1 = 0.f;
        if (warp == 0) {
            x0 = __ldg(&x_in[2 * t]);            // prefetch input before the wait
            x1 = __ldg(&x_in[2 * t + 1]);
            // concurrent 4-way discovery: lanes 0..3 poll their quarter counter
            // (4 separate L2 lines), ballot-exit when all quarters complete.
            bool ok = (lane >= 4);
            const unsigned* qp = &g_q[lane & 3][t];
            unsigned bal;
            do {
                if (!ok) ok = ((int)(ld_relaxed_u32(qp) - tq) >= 0);
                bal = __ballot_sync(0xffffffffu, ok);
            } while (bal != 0xffffffffu);
        }
        __syncthreads();

        // ---- load state: 4 coalesced float4 (rows 2p, 2p+1 per float4) ----
        const float2* srow = g_state[rb];
        float4 st[4];
        #pragma unroll
        for (int k = 0; k < 4; k++) {
            const int p = k * NTHREADS + tid;
            st[k] = __ldcg(reinterpret_cast<const float4*>(&srow[2 * p]));
        }

        // ---- dot products, chunk-major (bit-identical per-accumulator order) ----
        float acc[16];
        #pragma unroll
        for (int c = 0; c < CPT; c++) {
            const float4 w = *reinterpret_cast<const float4*>(&Wc[c * CSTRF + tid * 4]);
            float a = 0.f;
            a = fmaf(st[0].x, w.x, a);
            a = fmaf(st[0].y, w.y, a);
            a = fmaf(st[0].z, w.z, a);
            a = fmaf(st[0].w, w.w, a);
            acc[c] = a;
        }
        #pragma unroll
        for (int kk = 0; kk < 3; kk++) {
            const float4 sv = st[kk + 1];
            #pragma unroll
            for (int c = 0; c < CPT; c++) {
                const float4 w = wr[c][kk];
                float a = acc[c];
                a = fmaf(sv.x, w.x, a);
                a = fmaf(sv.y, w.y, a);
                a = fmaf(sv.z, w.z, a);
                a = fmaf(sv.w, w.w, a);
                acc[c] = a;
            }
        }
        acc[14] = 0.f;
        acc[15] = 0.f;

        // ---- butterfly multi-column reduce: 16 SHFL + 16 FADD per warp ----
        #pragma unroll
        for (int i = 0; i < 8; i++) {
            const float give = (lane & 16) ? acc[i] : acc[i + 8];
            const float got  = __shfl_xor_sync(0xffffffffu, give, 16);
            const float keep = (lane & 16) ? acc[i + 8] : acc[i];
            acc[i] = keep + got;
        }
        #pragma unroll
        for (int i = 0; i < 4; i++) {
            const float give = (lane & 8) ? acc[i] : acc[i + 4];
            const float got  = __shfl_xor_sync(0xffffffffu, give, 8);
            const float keep = (lane & 8) ? acc[i + 4] : acc[i];
            acc[i] = keep + got;
        }
        #pragma unroll
        for (int i = 0; i < 2; i++) {
            const float give = (lane & 4) ? acc[i] : acc[i + 2];
            const float got  = __shfl_xor_sync(0xffffffffu, give, 4);
            const float keep = (lane & 4) ? acc[i + 2] : acc[i];
            acc[i] = keep + got;
        }
        {
            const float give = (lane & 2) ? acc[0] : acc[1];
            const float got  = __shfl_xor_sync(0xffffffffu, give, 2);
            const float keep = (lane & 2) ? acc[1] : acc[0];
            acc[0] = keep + got;
        }
        acc[0] += __shfl_xor_sync(0xffffffffu, acc[0], 1);

        if ((lane & 1) == 0) red[((lane >> 1) & 15) * NWARPS + warp] = acc[0];
        __syncthreads();

        if (warp == 0) {
            float r0 = 0.f, r1 = 0.f;
            float s_new = 0.f, gd = 0.f, spk = 0.f, v_new = 0.f;
            if (active) {
                const float4 p0 = *reinterpret_cast<const float4*>(&red[lane * NWARPS]);
                const float4 p1 = *reinterpret_cast<const float4*>(&red[lane * NWARPS + 4]);
                const float sum = ((p0.x + p0.y) + (p0.z + p0.w)) +
                                  ((p1.x + p1.y) + (p1.z + p1.w));

                const float I_tot  = sum + x0 * wi0 + x1 * wi1 + io;
                const float dv     = (I_tot - v) / 10.0f;          // TAU_M
                const float v_next = v + dv;
                const float gating = fminf(fmaxf(v_next, -1.f), 1.f);
                const float dvc    = fminf(fmaxf(dv, -1.f), 1.f);
                gd                 = gating * dvc;
                s_new              = s + (gd - s) / 10.0f;         // TAU_S
                spk                = (v_next >=  1.f) ? 1.f : 0.f;
                const float sn     = (v_next <= -1.f) ? 1.f : 0.f;
                v_new              = (1.f + spk - sn) * v_next;    // matches reference exactly

                v = v_new; s = s_new;
                __stcg(&g_state[wb][j], make_float2(s_new, gd));
            }
            // publish progress FIRST (release orders the state stores above)
            if (lane == 0) red_release_add(&g_q[myq][t + 1], 1u);

            // non-critical outputs after the release
            if (active) {
                out_spikes[(size_t)t * NN + j] = spk;
                out_vs[(size_t)t * NN + j]     = v_new;
                r0 = o0 * s_new;
                r1 = o1 * s_new;
            }
            #pragma unroll
            for (int o = 16; o; o >>= 1) {
                r0 += __shfl_down_sync(0xffffffffu, r0, o);
                r1 += __shfl_down_sync(0xffffffffu, r1, o);
            }
            if (lane == 0) {
                g_part[((size_t)t * G + b) * 2 + 0] = r0;
                g_part[((size_t)t * G + b) * 2 + 1] = r1;
            }
        }
    }

    // bump this quarter's epoch slot (one per CTA per replay)
    if (warp == 0 && lane == 0) red_release_add(&g_q[myq][TT + 1], 1u);
}

// epilogue: one warp per timestep, coalesced float2 loads + shfl reduce
__global__ void readout_kernel(float* __restrict__ out_ro) {
    const int t    = blockIdx.x * (blockDim.x >> 5) + (threadIdx.x >> 5);
    const int lane = threadIdx.x & 31;
    if (t < TT) {
        const float2* p = reinterpret_cast<const float2*>(&g_part[(size_t)t * G * 2]);
        float a = 0.f, c = 0.f;
        for (int bb = lane; bb < G; bb += 32) {
            const float2 pv = p[bb];
            a += pv.x;
            c += pv.y;
        }
        #pragma unroll
        for (int o = 16; o; o >>= 1) {
            a += __shfl_down_sync(0xffffffffu, a, o);
            c += __shfl_down_sync(0xffffffffu, c, o);
        }
        if (lane == 0) {
            out_ro[2 * t]     = a;
            out_ro[2 * t + 1] = c;
        }
    }
}

extern "C" void kernel_launch(void* const* d_in, const int* in_sizes, int n_in,
                              void* d_out, int out_size) {
    const float* x_in   = (const float*)d_in[0];
    const float* W_syn  = (const float*)d_in[1];
    const float* W_fast = (const float*)d_in[2];
    const float* W_in   = (const float*)d_in[3];
    const float* I_o    = (const float*)d_in[4];
    const float* O      = (const float*)d_in[5];

    float* out        = (float*)d_out;
    float* out_spikes = out;                                // [T][N]
    float* out_ro     = out + (size_t)TT * NN;              // [T][2]
    float* out_vs     = out + (size_t)TT * NN + 2 * TT;     // [T][N]

    cudaFuncSetAttribute(nlif_kernel,
                         cudaFuncAttributeMaxDynamicSharedMemorySize, SMEM_BYTES);

    nlif_kernel<<<G, NTHREADS, SMEM_BYTES>>>(x_in, W_syn, W_fast, W_in, I_o, O,
                                             out_spikes, out_vs);
    // 8 warps per block, one warp per timestep
    readout_kernel<<<TT / 8, NTHREADS>>>(out_ro);
}

// round 15
// speedup vs baseline: 1.9621x; 1.0957x over previous
#include <cuda_runtime.h>

// ---------------------------------------------------------------------------
// NLIF recurrent spiking net — persistent kernel.
// Round 15: R11 exactly (single-counter sync locked), plus ONE change:
// 4x-replicated state vector. Producers store (s,s_fast) to 4 copies 16KB
// apart; CTA b reads copy b&3. Per-L2-line read fan-in drops 147 -> ~37,
// quartering the per-step slice-serial drain of the state broadcast.
// ---------------------------------------------------------------------------

#define NN 2048
#define TT 2048
#define G  147           // CTAs, 1 per SM (all co-resident on 148 SMs)
#define CPT 14           // columns per CTA (147*14 = 2058 >= 2048)
#define NTHREADS 256
#define NWARPS 8
#define CSTRF 4096       // floats per column slab: 2048 rows x (ws,wf)
#define NCOPY 4          // state replication factor

#define SMEM_BYTES ((CPT * CSTRF + 16 * NWARPS) * 4)

// persistent device state (no allocations allowed)
__device__ __align__(16) float2 g_state[2][NCOPY][NN];  // (s, s_fast) x 4 copies
__device__ unsigned g_cnt[TT + 2];                      // per-step counters + epoch slot
__device__ float g_part[TT * G * 2];                    // per-CTA readout partials

__device__ __forceinline__ unsigned ld_relaxed_u32(const unsigned* p) {
    unsigned v;
    asm volatile("ld.relaxed.gpu.global.u32 %0, [%1];" : "=r"(v) : "l"(p) : "memory");
    return v;
}
__device__ __forceinline__ void red_release_add(unsigned* p, unsigned v) {
    asm volatile("red.release.gpu.global.add.u32 [%0], %1;" :: "l"(p), "r"(v) : "memory");
}

__global__ void __launch_bounds__(NTHREADS, 1)
nlif_kernel(const float* __restrict__ x_in,    // [T][2]
            const float* __restrict__ W_syn,   // [N][N]
            const float* __restrict__ W_fast,  // [N][N]
            const float* __restrict__ W_in,    // [2][N]
            const float* __restrict__ I_o,     // [N]
            const float* __restrict__ O,       // [2][N]
            float* __restrict__ out_spikes,    // [T][N]
            float* __restrict__ out_vs)        // [T][N]
{
    extern __shared__ float smem[];
    float* Wc  = smem;                    // [CPT][CSTRF] : per pair p, (ws0,wf0,ws1,wf1)
    float* red = smem + CPT * CSTRF;      // [16][NWARPS]

    const int tid  = threadIdx.x;
    const int warp = tid >> 5;
    const int lane = tid & 31;
    const int b    = blockIdx.x;
    const int j0   = b * CPT;
    const int mycp = b & (NCOPY - 1);     // which state copy this CTA reads

    // epoch base: all counters equal R*G at launch start; slot TT+1 is bumped
    // once per CTA at kernel end, so it reads exactly R*G here.
    const unsigned base = ld_relaxed_u32(&g_cnt[TT + 1]);
    const unsigned tgt0 = base + (unsigned)G;

    // ---- stage weight columns into SMEM, interleaved (ws,wf) per row ----
    for (int i = warp; i < NN; i += NWARPS) {
        if (lane < CPT) {
            const int jj = j0 + lane;
            float ws = 0.f, wf = 0.f;
            if (jj < NN) {
                ws = W_syn[(size_t)i * NN + jj];
                wf = W_fast[(size_t)i * NN + jj];
                if (i == jj) ws = 0.f;              // self-recurrence mask
            }
            const int p = i >> 1, r = i & 1;
            Wc[lane * CSTRF + p * 4 + r * 2 + 0] = ws;
            Wc[lane * CSTRF + p * 4 + r * 2 + 1] = wf;
        }
    }
    __syncthreads();

    // ---- pull k=1,2,3 weight chunks into registers (168 regs/thread) ----
    float4 wr[CPT][3];
    #pragma unroll
    for (int c = 0; c < CPT; c++) {
        #pragma unroll
        for (int kk = 0; kk < 3; kk++) {
            const int p = (kk + 1) * NTHREADS + tid;
            wr[c][kk] = *reinterpret_cast<const float4*>(&Wc[c * CSTRF + p * 4]);
        }
    }

    // ---- per-column persistent state in warp-0 registers ----
    const int j = j0 + lane;
    const bool active = (warp == 0) && (lane < CPT) && (j < NN);
    float v = 0.f, s = 0.f;
    float wi0 = 0.f, wi1 = 0.f, io = 0.f, o0 = 0.f, o1 = 0.f;
    if (active) {
        wi0 = W_in[j];
        wi1 = W_in[NN + j];
        io  = I_o[j];
        o0  = O[j];
        o1  = O[NN + j];
        #pragma unroll
        for (int cp = 0; cp < NCOPY; cp++)            // t=0 reads parity-0 zeros
            __stcg(&g_state[0][cp][j], make_float2(0.f, 0.f));
    }
    if (warp == 0 && lane == 0) red_release_add(&g_cnt[0], 1u);  // initial publish

    for (int t = 0; t < TT; t++) {
        const int rb = t & 1;
        const int wb = rb ^ 1;

        float x0 = 0.f, x1 = 0.f;
        if (warp == 0) {
            x0 = __ldg(&x_in[2 * t]);            // prefetch input before the wait
            x1 = __ldg(&x_in[2 * t + 1]);
            // relaxed hot-spin on the single counter (R11 sync, locked)
            const unsigned* cp = &g_cnt[t];
            unsigned f = ld_relaxed_u32(cp);
            while ((int)(f - tgt0) < 0) {
                f = ld_relaxed_u32(cp);
            }
        }
        __syncthreads();

        // ---- load state from THIS CTA's copy: 4 coalesced float4 ----
        const float2* srow = g_state[rb][mycp];
        float4 st[4];
        #pragma unroll
        for (int k = 0; k < 4; k++) {
            const int p = k * NTHREADS + tid;
            st[k] = __ldcg(reinterpret_cast<const float4*>(&srow[2 * p]));
        }

        // ---- dot products, chunk-major (bit-identical per-accumulator order) ----
        float acc[16];
        #pragma unroll
        for (int c = 0; c < CPT; c++) {
            const float4 w = *reinterpret_cast<const float4*>(&Wc[c * CSTRF + tid * 4]);
            float a = 0.f;
            a = fmaf(st[0].x, w.x, a);
            a = fmaf(st[0].y, w.y, a);
            a = fmaf(st[0].z, w.z, a);
            a = fmaf(st[0].w, w.w, a);
            acc[c] = a;
        }
        #pragma unroll
        for (int kk = 0; kk < 3; kk++) {
            const float4 sv = st[kk + 1];
            #pragma unroll
            for (int c = 0; c < CPT; c++) {
                const float4 w = wr[c][kk];
                float a = acc[c];
                a = fmaf(sv.x, w.x, a);
                a = fmaf(sv.y, w.y, a);
                a = fmaf(sv.z, w.z, a);
                a = fmaf(sv.w, w.w, a);
                acc[c] = a;
            }
        }
        acc[14] = 0.f;
        acc[15] = 0.f;

        // ---- butterfly multi-column reduce: 16 SHFL + 16 FADD per warp ----
        #pragma unroll
        for (int i = 0; i < 8; i++) {
            const float give = (lane & 16) ? acc[i] : acc[i + 8];
            const float got  = __shfl_xor_sync(0xffffffffu, give, 16);
            const float keep = (lane & 16) ? acc[i + 8] : acc[i];
            acc[i] = keep + got;
        }
        #pragma unroll
        for (int i = 0; i < 4; i++) {
            const float give = (lane & 8) ? acc[i] : acc[i + 4];
            const float got  = __shfl_xor_sync(0xffffffffu, give, 8);
            const float keep = (lane & 8) ? acc[i + 4] : acc[i];
            acc[i] = keep + got;
        }
        #pragma unroll
        for (int i = 0; i < 2; i++) {
            const float give = (lane & 4) ? acc[i] : acc[i + 2];
            const float got  = __shfl_xor_sync(0xffffffffu, give, 4);
            const float keep = (lane & 4) ? acc[i + 2] : acc[i];
            acc[i] = keep + got;
        }
        {
            const float give = (lane & 2) ? acc[0] : acc[1];
            const float got  = __shfl_xor_sync(0xffffffffu, give, 2);
            const float keep = (lane & 2) ? acc[1] : acc[0];
            acc[0] = keep + got;
        }
        acc[0] += __shfl_xor_sync(0xffffffffu, acc[0], 1);

        if ((lane & 1) == 0) red[((lane >> 1) & 15) * NWARPS + warp] = acc[0];
        __syncthreads();

        if (warp == 0) {
            float r0 = 0.f, r1 = 0.f;
            float s_new = 0.f, gd = 0.f, spk = 0.f, v_new = 0.f;
            if (active) {
                const float4 p0 = *reinterpret_cast<const float4*>(&red[lane * NWARPS]);
                const float4 p1 = *reinterpret_cast<const float4*>(&red[lane * NWARPS + 4]);
                const float sum = ((p0.x + p0.y) + (p0.z + p0.w)) +
                                  ((p1.x + p1.y) + (p1.z + p1.w));

                const float I_tot  = sum + x0 * wi0 + x1 * wi1 + io;
                const float dv     = (I_tot - v) / 10.0f;          // TAU_M
                const float v_next = v + dv;
                const float gating = fminf(fmaxf(v_next, -1.f), 1.f);
                const float dvc    = fminf(fmaxf(dv, -1.f), 1.f);
                gd                 = gating * dvc;
                s_new              = s + (gd - s) / 10.0f;         // TAU_S
                spk                = (v_next >=  1.f) ? 1.f : 0.f;
                const float sn     = (v_next <= -1.f) ? 1.f : 0.f;
                v_new              = (1.f + spk - sn) * v_next;    // matches reference exactly

                v = v_new; s = s_new;
                const float2 sv2 = make_float2(s_new, gd);
                #pragma unroll
                for (int cp = 0; cp < NCOPY; cp++)
                    __stcg(&g_state[wb][cp][j], sv2);
            }
            // publish progress FIRST (release orders the state stores above)
            if (lane == 0) red_release_add(&g_cnt[t + 1], 1u);

            // non-critical outputs after the release
            if (active) {
                out_spikes[(size_t)t * NN + j] = spk;
                out_vs[(size_t)t * NN + j]     = v_new;
                r0 = o0 * s_new;
                r1 = o1 * s_new;
            }
            #pragma unroll
            for (int o = 16; o; o >>= 1) {
                r0 += __shfl_down_sync(0xffffffffu, r0, o);
                r1 += __shfl_down_sync(0xffffffffu, r1, o);
            }
            if (lane == 0) {
                g_part[((size_t)t * G + b) * 2 + 0] = r0;
                g_part[((size_t)t * G + b) * 2 + 1] = r1;
            }
        }
    }

    // bump the epoch slot (one per CTA per replay)
    if (warp == 0 && lane == 0) red_release_add(&g_cnt[TT + 1], 1u);
}

// epilogue: one warp per timestep, coalesced float2 loads + shfl reduce
__global__ void readout_kernel(float* __restrict__ out_ro) {
    const int t    = blockIdx.x * (blockDim.x >> 5) + (threadIdx.x >> 5);
    const int lane = threadIdx.x & 31;
    if (t < TT) {
        const float2* p = reinterpret_cast<const float2*>(&g_part[(size_t)t * G * 2]);
        float a = 0.f, c = 0.f;
        for (int bb = lane; bb < G; bb += 32) {
            const float2 pv = p[bb];
            a += pv.x;
            c += pv.y;
        }
        #pragma unroll
        for (int o = 16; o; o >>= 1) {
            a += __shfl_down_sync(0xffffffffu, a, o);
            c += __shfl_down_sync(0xffffffffu, c, o);
        }
        if (lane == 0) {
            out_ro[2 * t]     = a;
            out_ro[2 * t + 1] = c;
        }
    }
}

extern "C" void kernel_launch(void* const* d_in, const int* in_sizes, int n_in,
                              void* d_out, int out_size) {
    const float* x_in   = (const float*)d_in[0];
    const float* W_syn  = (const float*)d_in[1];
    const float* W_fast = (const float*)d_in[2];
    const float* W_in   = (const float*)d_in[3];
    const float* I_o    = (const float*)d_in[4];
    const float* O      = (const float*)d_in[5];

    float* out        = (float*)d_out;
    float* out_spikes = out;                                // [T][N]
    float* out_ro     = out + (size_t)TT * NN;              // [T][2]
    float* out_vs     = out + (size_t)TT * NN + 2 * TT;     // [T][N]

    cudaFuncSetAttribute(nlif_kernel,
                         cudaFuncAttributeMaxDynamicSharedMemorySize, SMEM_BYTES);

    nlif_kernel<<<G, NTHREADS, SMEM_BYTES>>>(x_in, W_syn, W_fast, W_in, I_o, O,
                                             out_spikes, out_vs);
    // 8 warps per block, one warp per timestep
    readout_kernel<<<TT / 8, NTHREADS>>>(out_ro);
}

// round 16
// speedup vs baseline: 2.0326x; 1.0359x over previous
#include <cuda_runtime.h>

// ---------------------------------------------------------------------------
// NLIF recurrent spiking net — persistent kernel.
// Round 16: R11 exactly (sync + compute core locked), tail trim only:
//  - external-input term hoisted before bar#1 (off the release path)
//  - /10.0f -> *0.1f (removes two serial FDIVs from the release path)
// ---------------------------------------------------------------------------

#define NN 2048
#define TT 2048
#define G  147           // CTAs, 1 per SM (all co-resident on 148 SMs)
#define CPT 14           // columns per CTA (147*14 = 2058 >= 2048)
#define NTHREADS 256
#define NWARPS 8
#define CSTRF 4096       // floats per column slab: 2048 rows x (ws,wf)

#define SMEM_BYTES ((CPT * CSTRF + 16 * NWARPS) * 4)

// persistent device state (no allocations allowed)
__device__ __align__(16) float2 g_state[2][NN];   // (s, s_fast), double-buffered
__device__ unsigned g_cnt[TT + 2];                // per-step counters + epoch slot
__device__ float g_part[TT * G * 2];              // per-CTA readout partials

__device__ __forceinline__ unsigned ld_relaxed_u32(const unsigned* p) {
    unsigned v;
    asm volatile("ld.relaxed.gpu.global.u32 %0, [%1];" : "=r"(v) : "l"(p) : "memory");
    return v;
}
__device__ __forceinline__ void red_release_add(unsigned* p, unsigned v) {
    asm volatile("red.release.gpu.global.add.u32 [%0], %1;" :: "l"(p), "r"(v) : "memory");
}

__global__ void __launch_bounds__(NTHREADS, 1)
nlif_kernel(const float* __restrict__ x_in,    // [T][2]
            const float* __restrict__ W_syn,   // [N][N]
            const float* __restrict__ W_fast,  // [N][N]
            const float* __restrict__ W_in,    // [2][N]
            const float* __restrict__ I_o,     // [N]
            const float* __restrict__ O,       // [2][N]
            float* __restrict__ out_spikes,    // [T][N]
            float* __restrict__ out_vs)        // [T][N]
{
    extern __shared__ float smem[];
    float* Wc  = smem;                    // [CPT][CSTRF] : per pair p, (ws0,wf0,ws1,wf1)
    float* red = smem + CPT * CSTRF;      // [16][NWARPS]

    const int tid  = threadIdx.x;
    const int warp = tid >> 5;
    const int lane = tid & 31;
    const int b    = blockIdx.x;
    const int j0   = b * CPT;

    // epoch base: all counters equal R*G at launch start; slot TT+1 is bumped
    // once per CTA at kernel end, so it reads exactly R*G here.
    const unsigned base = ld_relaxed_u32(&g_cnt[TT + 1]);
    const unsigned tgt0 = base + (unsigned)G;

    // ---- stage weight columns into SMEM, interleaved (ws,wf) per row ----
    for (int i = warp; i < NN; i += NWARPS) {
        if (lane < CPT) {
            const int jj = j0 + lane;
            float ws = 0.f, wf = 0.f;
            if (jj < NN) {
                ws = W_syn[(size_t)i * NN + jj];
                wf = W_fast[(size_t)i * NN + jj];
                if (i == jj) ws = 0.f;              // self-recurrence mask
            }
            const int p = i >> 1, r = i & 1;
            Wc[lane * CSTRF + p * 4 + r * 2 + 0] = ws;
            Wc[lane * CSTRF + p * 4 + r * 2 + 1] = wf;
        }
    }
    __syncthreads();

    // ---- pull k=1,2,3 weight chunks into registers (168 regs/thread) ----
    float4 wr[CPT][3];
    #pragma unroll
    for (int c = 0; c < CPT; c++) {
        #pragma unroll
        for (int kk = 0; kk < 3; kk++) {
            const int p = (kk + 1) * NTHREADS + tid;
            wr[c][kk] = *reinterpret_cast<const float4*>(&Wc[c * CSTRF + p * 4]);
        }
    }

    // ---- per-column persistent state in warp-0 registers ----
    const int j = j0 + lane;
    const bool active = (warp == 0) && (lane < CPT) && (j < NN);
    float v = 0.f, s = 0.f;
    float wi0 = 0.f, wi1 = 0.f, io = 0.f, o0 = 0.f, o1 = 0.f;
    if (active) {
        wi0 = W_in[j];
        wi1 = W_in[NN + j];
        io  = I_o[j];
        o0  = O[j];
        o1  = O[NN + j];
        __stcg(&g_state[0][j], make_float2(0.f, 0.f));   // t=0 reads parity-0 zeros
    }
    if (warp == 0 && lane == 0) red_release_add(&g_cnt[0], 1u);  // initial publish

    for (int t = 0; t < TT; t++) {
        const int rb = t & 1;
        const int wb = rb ^ 1;

        float ext = 0.f;                 // external-input term, off the tail path
        if (warp == 0) {
            const float x0 = __ldg(&x_in[2 * t]);
            const float x1 = __ldg(&x_in[2 * t + 1]);
            // relaxed hot-spin on the single counter (R11 sync, locked)
            const unsigned* cp = &g_cnt[t];
            unsigned f = ld_relaxed_u32(cp);
            while ((int)(f - tgt0) < 0) {
                f = ld_relaxed_u32(cp);
            }
            ext = fmaf(x1, wi1, fmaf(x0, wi0, io));   // hoisted out of the tail
        }
        __syncthreads();

        // ---- load state: 4 coalesced float4 (rows 2p, 2p+1 per float4) ----
        const float2* srow = g_state[rb];
        float4 st[4];
        #pragma unroll
        for (int k = 0; k < 4; k++) {
            const int p = k * NTHREADS + tid;
            st[k] = __ldcg(reinterpret_cast<const float4*>(&srow[2 * p]));
        }

        // ---- dot products, chunk-major (bit-identical per-accumulator order) ----
        float acc[16];
        #pragma unroll
        for (int c = 0; c < CPT; c++) {
            const float4 w = *reinterpret_cast<const float4*>(&Wc[c * CSTRF + tid * 4]);
            float a = 0.f;
            a = fmaf(st[0].x, w.x, a);
            a = fmaf(st[0].y, w.y, a);
            a = fmaf(st[0].z, w.z, a);
            a = fmaf(st[0].w, w.w, a);
            acc[c] = a;
        }
        #pragma unroll
        for (int kk = 0; kk < 3; kk++) {
            const float4 sv = st[kk + 1];
            #pragma unroll
            for (int c = 0; c < CPT; c++) {
                const float4 w = wr[c][kk];
                float a = acc[c];
                a = fmaf(sv.x, w.x, a);
                a = fmaf(sv.y, w.y, a);
                a = fmaf(sv.z, w.z, a);
                a = fmaf(sv.w, w.w, a);
                acc[c] = a;
            }
        }
        acc[14] = 0.f;
        acc[15] = 0.f;

        // ---- butterfly multi-column reduce: 16 SHFL + 16 FADD per warp ----
        #pragma unroll
        for (int i = 0; i < 8; i++) {
            const float give = (lane & 16) ? acc[i] : acc[i + 8];
            const float got  = __shfl_xor_sync(0xffffffffu, give, 16);
            const float keep = (lane & 16) ? acc[i + 8] : acc[i];
            acc[i] = keep + got;
        }
        #pragma unroll
        for (int i = 0; i < 4; i++) {
            const float give = (lane & 8) ? acc[i] : acc[i + 4];
            const float got  = __shfl_xor_sync(0xffffffffu, give, 8);
            const float keep = (lane & 8) ? acc[i + 4] : acc[i];
            acc[i] = keep + got;
        }
        #pragma unroll
        for (int i = 0; i < 2; i++) {
            const float give = (lane & 4) ? acc[i] : acc[i + 2];
            const float got  = __shfl_xor_sync(0xffffffffu, give, 4);
            const float keep = (lane & 4) ? acc[i + 2] : acc[i];
            acc[i] = keep + got;
        }
        {
            const float give = (lane & 2) ? acc[0] : acc[1];
            const float got  = __shfl_xor_sync(0xffffffffu, give, 2);
            const float keep = (lane & 2) ? acc[1] : acc[0];
            acc[0] = keep + got;
        }
        acc[0] += __shfl_xor_sync(0xffffffffu, acc[0], 1);

        if ((lane & 1) == 0) red[((lane >> 1) & 15) * NWARPS + warp] = acc[0];
        __syncthreads();

        if (warp == 0) {
            float r0 = 0.f, r1 = 0.f;
            float s_new = 0.f, gd = 0.f, spk = 0.f, v_new = 0.f;
            if (active) {
                const float4 p0 = *reinterpret_cast<const float4*>(&red[lane * NWARPS]);
                const float4 p1 = *reinterpret_cast<const float4*>(&red[lane * NWARPS + 4]);
                const float sum = ((p0.x + p0.y) + (p0.z + p0.w)) +
                                  ((p1.x + p1.y) + (p1.z + p1.w));

                const float I_tot  = sum + ext;
                const float dv     = (I_tot - v) * 0.1f;           // 1/TAU_M (mul, no FDIV)
                const float v_next = v + dv;
                const float gating = fminf(fmaxf(v_next, -1.f), 1.f);
                const float dvc    = fminf(fmaxf(dv, -1.f), 1.f);
                gd                 = gating * dvc;
                s_new              = s + (gd - s) * 0.1f;          // 1/TAU_S (mul, no FDIV)
                spk                = (v_next >=  1.f) ? 1.f : 0.f;
                const float sn     = (v_next <= -1.f) ? 1.f : 0.f;
                v_new              = (1.f + spk - sn) * v_next;    // matches reference exactly

                v = v_new; s = s_new;
                __stcg(&g_state[wb][j], make_float2(s_new, gd));
            }
            // publish progress FIRST (release orders the state stores above)
            if (lane == 0) red_release_add(&g_cnt[t + 1], 1u);

            // non-critical outputs after the release
            if (active) {
                out_spikes[(size_t)t * NN + j] = spk;
                out_vs[(size_t)t * NN + j]     = v_new;
                r0 = o0 * s_new;
                r1 = o1 * s_new;
            }
            #pragma unroll
            for (int o = 16; o; o >>= 1) {
                r0 += __shfl_down_sync(0xffffffffu, r0, o);
                r1 += __shfl_down_sync(0xffffffffu, r1, o);
            }
            if (lane == 0) {
                g_part[((size_t)t * G + b) * 2 + 0] = r0;
                g_part[((size_t)t * G + b) * 2 + 1] = r1;
            }
        }
    }

    // bump the epoch slot (one per CTA per replay)
    if (warp == 0 && lane == 0) red_release_add(&g_cnt[TT + 1], 1u);
}

// epilogue: one warp per timestep, coalesced float2 loads + shfl reduce
__global__ void readout_kernel(float* __restrict__ out_ro) {
    const int t    = blockIdx.x * (blockDim.x >> 5) + (threadIdx.x >> 5);
    const int lane = threadIdx.x & 31;
    if (t < TT) {
        const float2* p = reinterpret_cast<const float2*>(&g_part[(size_t)t * G * 2]);
        float a = 0.f, c = 0.f;
        for (int bb = lane; bb < G; bb += 32) {
            const float2 pv = p[bb];
            a += pv.x;
            c += pv.y;
        }
        #pragma unroll
        for (int o = 16; o; o >>= 1) {
            a += __shfl_down_sync(0xffffffffu, a, o);
            c += __shfl_down_sync(0xffffffffu, c, o);
        }
        if (lane == 0) {
            out_ro[2 * t]     = a;
            out_ro[2 * t + 1] = c;
        }
    }
}

extern "C" void kernel_launch(void* const* d_in, const int* in_sizes, int n_in,
                              void* d_out, int out_size) {
    const float* x_in   = (const float*)d_in[0];
    const float* W_syn  = (const float*)d_in[1];
    const float* W_fast = (const float*)d_in[2];
    const float* W_in   = (const float*)d_in[3];
    const float* I_o    = (const float*)d_in[4];
    const float* O      = (const float*)d_in[5];

    float* out        = (float*)d_out;
    float* out_spikes = out;                                // [T][N]
    float* out_ro     = out + (size_t)TT * NN;              // [T][2]
    float* out_vs     = out + (size_t)TT * NN + 2 * TT;     // [T][N]

    cudaFuncSetAttribute(nlif_kernel,
                         cudaFuncAttributeMaxDynamicSharedMemorySize, SMEM_BYTES);

    nlif_kernel<<<G, NTHREADS, SMEM_BYTES>>>(x_in, W_syn, W_fast, W_in, I_o, O,
                                             out_spikes, out_vs);
    // 8 warps per block, one warp per timestep
    readout_kernel<<<TT / 8, NTHREADS>>>(out_ro);
}